// round 1
// baseline (speedup 1.0000x reference)
#include <cuda_runtime.h>
#include <cuda_bf16.h>
#include <mma.h>

using namespace nvcuda;

// Problem constants
#define BB   512
#define TT   128
#define DIN  256
#define HH   1024
#define FH   4096           // 4*HH
#define TBROWS (TT*BB)      // 65536
#define LBL  3

// GEMM tiling
#define BM 128
#define BN 128
#define BK 32
#define ASTRIDE (BK+8)      // 40 (conflict-free for ldmatrix)
#define BSTRIDE (BN+8)      // 136

// ---------------- scratch (device globals: no allocation allowed) ----------
__device__ float d_Xtm[(size_t)TBROWS*DIN];     // time-major input  [T*B, 256]
__device__ float d_Z[(size_t)TBROWS*FH];        // pre-activations   [T*B, 4096] (reused for both layers)
__device__ float d_H1all[(size_t)TBROWS*HH];    // layer-1 hidden states, all timesteps
__device__ float d_h1[BB*HH], d_c1[BB*HH];
__device__ float d_h2[BB*HH], d_c2[BB*HH];
__device__ float d_hidden[BB*HH];               // gathered last-valid h2 per batch

// bf16 split weights (hi/lo)
__device__ __nv_bfloat16 d_W1h[(size_t)DIN*FH], d_W1l[(size_t)DIN*FH];
__device__ __nv_bfloat16 d_U1h[(size_t)HH*FH],  d_U1l[(size_t)HH*FH];
__device__ __nv_bfloat16 d_W2h[(size_t)HH*FH],  d_W2l[(size_t)HH*FH];
__device__ __nv_bfloat16 d_U2h[(size_t)HH*FH],  d_U2l[(size_t)HH*FH];

// ---------------- helper kernels -------------------------------------------

// split fp32 weight matrix into bf16 hi/lo pair
__global__ void split_weight(const float* __restrict__ W,
                             __nv_bfloat16* __restrict__ hi,
                             __nv_bfloat16* __restrict__ lo, int n)
{
    int i = blockIdx.x * blockDim.x + threadIdx.x;
    if (i < n) {
        float x = W[i];
        __nv_bfloat16 h = __float2bfloat16(x);
        hi[i] = h;
        lo[i] = __float2bfloat16(x - __bfloat162float(h));
    }
}

// chars [B][T][DIN] -> Xtm [T][B][DIN]  (float4 granularity)
__global__ void transpose_chars(const float* __restrict__ chars, float* __restrict__ Xtm)
{
    int idx = blockIdx.x * blockDim.x + threadIdx.x;  // over TBROWS*DIN/4
    int d4 = idx & (DIN/4 - 1);
    int rest = idx >> 6;                // / (DIN/4)
    int b = rest & (BB - 1);
    int t = rest >> 9;                  // / BB
    const float4* src = (const float4*)chars;
    float4* dst = (float4*)Xtm;
    dst[((size_t)t*BB + b)*(DIN/4) + d4] = src[((size_t)b*TT + t)*(DIN/4) + d4];
}

__global__ void init_states()
{
    int i = blockIdx.x * blockDim.x + threadIdx.x;
    if (i < BB*HH) { d_h1[i] = 0.f; d_c1[i] = 0.f; d_h2[i] = 0.f; d_c2[i] = 0.f; }
}

// LSTM gate elementwise: z [B,4H] (i,f,g,o keras order), c/h [B,H]
__global__ void lstm_gate(const float* __restrict__ z, const float* __restrict__ bias,
                          float* __restrict__ c, float* __restrict__ h,
                          float* __restrict__ hstore,        // layer1: H1all+t*B*H, else null
                          const int* __restrict__ seqlen,    // layer2: gather, else null
                          float* __restrict__ hidden, int t)
{
    int i = blockIdx.x * blockDim.x + threadIdx.x;  // B*H
    int b = i >> 10;
    int j = i & (HH - 1);
    const float* zr = z + (size_t)b * FH;
    float zi = zr[j]        + bias[j];
    float zf = zr[HH + j]   + bias[HH + j];
    float zg = zr[2*HH + j] + bias[2*HH + j];
    float zo = zr[3*HH + j] + bias[3*HH + j];
    float ig = 1.f / (1.f + __expf(-zi));
    float fg = 1.f / (1.f + __expf(-zf));
    float gg = tanhf(zg);
    float og = 1.f / (1.f + __expf(-zo));
    float cn = fg * c[i] + ig * gg;
    c[i] = cn;
    float hn = og * tanhf(cn);
    h[i] = hn;
    if (hstore) hstore[i] = hn;
    if (seqlen && (seqlen[b] - 1 == t)) hidden[i] = hn;
}

// out[b,:] = relu(hidden[b,:] @ Wd + bd)
__global__ void dense_relu(const float* __restrict__ hidden, const float* __restrict__ Wd,
                           const float* __restrict__ bd, float* __restrict__ out)
{
    __shared__ float buf[3][128];
    int b = blockIdx.x, tid = threadIdx.x;
    const float* hb = hidden + (size_t)b * HH;
    float s0 = 0.f, s1 = 0.f, s2 = 0.f;
    for (int k = tid; k < HH; k += 128) {
        float hv = hb[k];
        s0 = fmaf(hv, Wd[k*3 + 0], s0);
        s1 = fmaf(hv, Wd[k*3 + 1], s1);
        s2 = fmaf(hv, Wd[k*3 + 2], s2);
    }
    buf[0][tid] = s0; buf[1][tid] = s1; buf[2][tid] = s2;
    __syncthreads();
    for (int s = 64; s > 0; s >>= 1) {
        if (tid < s) {
            buf[0][tid] += buf[0][tid + s];
            buf[1][tid] += buf[1][tid + s];
            buf[2][tid] += buf[2][tid + s];
        }
        __syncthreads();
    }
    if (tid < 3) out[b*3 + tid] = fmaxf(buf[tid][0] + bd[tid], 0.f);
}

// ---------------- split-bf16 (3-MMA) GEMM ----------------------------------
// C[M,N] (+)= A[M,K] @ B[K,N], A fp32 (split on the fly), B pre-split bf16 hi/lo.
// CTA tile 128x128, BK=32, 8 warps as 2x4 (warp tile 64x32), two-stage pipeline.
__global__ void __launch_bounds__(256)
gemm_bf16x3(const float* __restrict__ A,
            const __nv_bfloat16* __restrict__ Bh, const __nv_bfloat16* __restrict__ Bl,
            float* __restrict__ C, int M, int N, int K, int accumulate)
{
    __shared__ __nv_bfloat16 sAh[BM][ASTRIDE];
    __shared__ __nv_bfloat16 sAl[BM][ASTRIDE];
    __shared__ __nv_bfloat16 sBh[BK][BSTRIDE];
    __shared__ __nv_bfloat16 sBl[BK][BSTRIDE];

    const int bm = blockIdx.y * BM;
    const int bn = blockIdx.x * BN;
    const int tid = threadIdx.x;
    const int warp = tid >> 5;
    const int wr = warp >> 2;   // 0..1 -> 64 rows
    const int wc = warp & 3;    // 0..3 -> 32 cols

    wmma::fragment<wmma::accumulator, 16, 16, 16, float> acc[4][2];
    if (accumulate) {
        #pragma unroll
        for (int m = 0; m < 4; m++)
            #pragma unroll
            for (int n = 0; n < 2; n++)
                wmma::load_matrix_sync(acc[m][n],
                    &C[(size_t)(bm + wr*64 + m*16)*N + bn + wc*32 + n*16],
                    N, wmma::mem_row_major);
    } else {
        #pragma unroll
        for (int m = 0; m < 4; m++)
            #pragma unroll
            for (int n = 0; n < 2; n++)
                wmma::fill_fragment(acc[m][n], 0.0f);
    }

    float4 aReg[4];
    uint4  bhReg[2], blReg[2];

    auto loadG = [&](int k0) {
        #pragma unroll
        for (int i = 0; i < 4; i++) {
            int idx = tid + (i << 8);
            int r = idx >> 3, c = (idx & 7) << 2;
            aReg[i] = *(const float4*)(A + (size_t)(bm + r)*K + k0 + c);
        }
        #pragma unroll
        for (int i = 0; i < 2; i++) {
            int idx = tid + (i << 8);
            int r = idx >> 4, c = (idx & 15) << 3;
            bhReg[i] = *(const uint4*)(Bh + (size_t)(k0 + r)*N + bn + c);
            blReg[i] = *(const uint4*)(Bl + (size_t)(k0 + r)*N + bn + c);
        }
    };
    auto storeS = [&]() {
        #pragma unroll
        for (int i = 0; i < 4; i++) {
            int idx = tid + (i << 8);
            int r = idx >> 3, c = (idx & 7) << 2;
            float vx = aReg[i].x, vy = aReg[i].y, vz = aReg[i].z, vw = aReg[i].w;
            __nv_bfloat16 hx = __float2bfloat16(vx), hy = __float2bfloat16(vy);
            __nv_bfloat16 hz = __float2bfloat16(vz), hw = __float2bfloat16(vw);
            __nv_bfloat162 hp0; hp0.x = hx; hp0.y = hy;
            __nv_bfloat162 hp1; hp1.x = hz; hp1.y = hw;
            *(__nv_bfloat162*)&sAh[r][c]     = hp0;
            *(__nv_bfloat162*)&sAh[r][c + 2] = hp1;
            __nv_bfloat162 lp0, lp1;
            lp0.x = __float2bfloat16(vx - __bfloat162float(hx));
            lp0.y = __float2bfloat16(vy - __bfloat162float(hy));
            lp1.x = __float2bfloat16(vz - __bfloat162float(hz));
            lp1.y = __float2bfloat16(vw - __bfloat162float(hw));
            *(__nv_bfloat162*)&sAl[r][c]     = lp0;
            *(__nv_bfloat162*)&sAl[r][c + 2] = lp1;
        }
        #pragma unroll
        for (int i = 0; i < 2; i++) {
            int idx = tid + (i << 8);
            int r = idx >> 4, c = (idx & 15) << 3;
            *(uint4*)&sBh[r][c] = bhReg[i];
            *(uint4*)&sBl[r][c] = blReg[i];
        }
    };
    auto compute = [&]() {
        #pragma unroll
        for (int kk = 0; kk < 2; kk++) {
            wmma::fragment<wmma::matrix_b, 16, 16, 16, __nv_bfloat16, wmma::row_major> fbh[2], fbl[2];
            #pragma unroll
            for (int n = 0; n < 2; n++) {
                wmma::load_matrix_sync(fbh[n], &sBh[kk*16][wc*32 + n*16], BSTRIDE);
                wmma::load_matrix_sync(fbl[n], &sBl[kk*16][wc*32 + n*16], BSTRIDE);
            }
            #pragma unroll
            for (int m = 0; m < 4; m++) {
                wmma::fragment<wmma::matrix_a, 16, 16, 16, __nv_bfloat16, wmma::row_major> fah, fal;
                wmma::load_matrix_sync(fah, &sAh[wr*64 + m*16][kk*16], ASTRIDE);
                wmma::load_matrix_sync(fal, &sAl[wr*64 + m*16][kk*16], ASTRIDE);
                #pragma unroll
                for (int n = 0; n < 2; n++) {
                    wmma::mma_sync(acc[m][n], fah, fbh[n], acc[m][n]);
                    wmma::mma_sync(acc[m][n], fal, fbh[n], acc[m][n]);
                    wmma::mma_sync(acc[m][n], fah, fbl[n], acc[m][n]);
                }
            }
        }
    };

    loadG(0);
    storeS();
    __syncthreads();
    for (int k0 = BK; k0 <= K; k0 += BK) {
        bool more = (k0 < K);
        if (more) loadG(k0);
        compute();
        if (more) {
            __syncthreads();
            storeS();
            __syncthreads();
        }
    }

    #pragma unroll
    for (int m = 0; m < 4; m++)
        #pragma unroll
        for (int n = 0; n < 2; n++)
            wmma::store_matrix_sync(&C[(size_t)(bm + wr*64 + m*16)*N + bn + wc*32 + n*16],
                                    acc[m][n], N, wmma::mem_row_major);
}

// ---------------- launch ----------------------------------------------------
extern "C" void kernel_launch(void* const* d_in, const int* in_sizes, int n_in,
                              void* d_out, int out_size)
{
    const float* chars  = (const float*)d_in[0];
    const int*   seqlen = (const int*)  d_in[1];
    const float* W1 = (const float*)d_in[2];
    const float* U1 = (const float*)d_in[3];
    const float* b1 = (const float*)d_in[4];
    const float* W2 = (const float*)d_in[5];
    const float* U2 = (const float*)d_in[6];
    const float* b2 = (const float*)d_in[7];
    const float* Wd = (const float*)d_in[8];
    const float* bd = (const float*)d_in[9];
    float* out = (float*)d_out;

    float *Xtm, *Z, *H1all, *h1, *c1, *h2, *c2, *hidden;
    __nv_bfloat16 *W1h, *W1l, *U1h, *U1l, *W2h, *W2l, *U2h, *U2l;
    cudaGetSymbolAddress((void**)&Xtm,    d_Xtm);
    cudaGetSymbolAddress((void**)&Z,      d_Z);
    cudaGetSymbolAddress((void**)&H1all,  d_H1all);
    cudaGetSymbolAddress((void**)&h1,     d_h1);
    cudaGetSymbolAddress((void**)&c1,     d_c1);
    cudaGetSymbolAddress((void**)&h2,     d_h2);
    cudaGetSymbolAddress((void**)&c2,     d_c2);
    cudaGetSymbolAddress((void**)&hidden, d_hidden);
    cudaGetSymbolAddress((void**)&W1h, d_W1h); cudaGetSymbolAddress((void**)&W1l, d_W1l);
    cudaGetSymbolAddress((void**)&U1h, d_U1h); cudaGetSymbolAddress((void**)&U1l, d_U1l);
    cudaGetSymbolAddress((void**)&W2h, d_W2h); cudaGetSymbolAddress((void**)&W2l, d_W2l);
    cudaGetSymbolAddress((void**)&U2h, d_U2h); cudaGetSymbolAddress((void**)&U2l, d_U2l);

    // weight splits (cheap, done each launch for determinism)
    split_weight<<<(DIN*FH + 255)/256, 256>>>(W1, W1h, W1l, DIN*FH);
    split_weight<<<(HH*FH  + 255)/256, 256>>>(U1, U1h, U1l, HH*FH);
    split_weight<<<(HH*FH  + 255)/256, 256>>>(W2, W2h, W2l, HH*FH);
    split_weight<<<(HH*FH  + 255)/256, 256>>>(U2, U2h, U2l, HH*FH);

    transpose_chars<<<(TBROWS*DIN/4)/256, 256>>>(chars, Xtm);
    init_states<<<(BB*HH)/256, 256>>>();

    dim3 blk(256);
    dim3 gBig(FH/BN, TBROWS/BM);   // (32, 512)
    dim3 gStep(FH/BN, BB/BM);      // (32, 4)
    const int gateBlocks = (BB*HH)/256;  // 2048

    // layer 1 input transform: Z = Xtm @ W1
    gemm_bf16x3<<<gBig, blk>>>(Xtm, W1h, W1l, Z, TBROWS, FH, DIN, 0);

    // layer 1 recurrence
    for (int t = 0; t < TT; t++) {
        float* zt = Z + (size_t)t * BB * FH;
        gemm_bf16x3<<<gStep, blk>>>(h1, U1h, U1l, zt, BB, FH, HH, 1);
        lstm_gate<<<gateBlocks, 256>>>(zt, b1, c1, h1,
                                       H1all + (size_t)t * BB * HH, nullptr, nullptr, t);
    }

    // layer 2 input transform: Z = H1all @ W2 (reuse Z)
    gemm_bf16x3<<<gBig, blk>>>(H1all, W2h, W2l, Z, TBROWS, FH, HH, 0);

    // layer 2 recurrence + last-valid gather
    for (int t = 0; t < TT; t++) {
        float* zt = Z + (size_t)t * BB * FH;
        gemm_bf16x3<<<gStep, blk>>>(h2, U2h, U2l, zt, BB, FH, HH, 1);
        lstm_gate<<<gateBlocks, 256>>>(zt, b2, c2, h2,
                                       nullptr, seqlen, hidden, t);
    }

    dense_relu<<<BB, 128>>>(hidden, Wd, bd, out);
}